// round 14
// baseline (speedup 1.0000x reference)
#include <cuda_runtime.h>
#include <cuda_fp16.h>
#include <math.h>
#include <stdint.h>

#define DINL __device__ __forceinline__

// ============================== scratch ====================================
struct Scalars {
  float s_in, sw1, sw2, swf1, swf2;
  float S1, s1, f1, S2;
};
__device__ Scalars g_s;
__device__ int g_xabsarr[256];
__device__ int g_wmaxarr[64];    // [tensor 4][block 16] float bits
__device__ int g_max1arr[256];
__device__ int g_max2arr[256];   // float bits (nonneg)

__device__ __align__(16) unsigned      g_qx [32 * 224 * 224];       // packed s8 3ch
__device__ __align__(16) unsigned char g_q1 [32u * 222 * 222 * 32]; // relu4 u8 NHWC
__device__ int g_pool[32 * 64];
__device__ __align__(16) unsigned g_w1p[9 * 32];
__device__ __align__(16) uint2    g_w2frag[18 * 8 * 32];  // fp16 B frags [(k*8+n)*32+lane]
__device__ signed char g_wf1q[128 * 64];
__device__ signed char g_wf2q[10 * 128];
__device__ int g_b1i[32];
__device__ int g_b2i[64];

// ============================== helpers ====================================
DINL int clamp_i(int v, int lo, int hi) { return v < lo ? lo : (v > hi ? hi : v); }

DINL uint32_t smem_u32(const void* p) {
  uint32_t a;
  asm("{ .reg .u64 t; cvta.to.shared.u64 t, %1; cvt.u32.u64 %0, t; }" : "=r"(a) : "l"(p));
  return a;
}

// exact u8(0..15) pair -> half2 via PRMT + HSUB2
DINL unsigned u8lo_to_h2(unsigned wv) {
  unsigned u = __byte_perm(wv, 0x64646464u, 0x4140);
  __half2 k; *(unsigned*)&k = 0x64006400u;
  __half2 r = __hsub2(*(__half2*)&u, k);
  return *(unsigned*)&r;
}
DINL unsigned u8hi_to_h2(unsigned wv) {
  unsigned u = __byte_perm(wv, 0x64646464u, 0x4342);
  __half2 k; *(unsigned*)&k = 0x64006400u;
  __half2 r = __hsub2(*(__half2*)&u, k);
  return *(unsigned*)&r;
}

// ============================== K0: init ===================================
__global__ void k_init() {
  int t = threadIdx.x;
  if (t < 256) { g_xabsarr[t] = 0; g_max1arr[t] = 0; g_max2arr[t] = 0; }
  if (t < 64) g_wmaxarr[t] = 0;
  for (int i = t; i < 2048; i += 256) g_pool[i] = 0;
}

// ============ K1: |x| max (float4) + weight maxes (merged) =================
__global__ void __launch_bounds__(256) k_abswmax(const float* __restrict__ x,
                                                 const float* __restrict__ w1,
                                                 const float* __restrict__ w2,
                                                 const float* __restrict__ wf1,
                                                 const float* __restrict__ wf2) {
  const int bx = blockIdx.x;
  float m = 0.f;
  if (bx < 2048) {
    const float4* __restrict__ x4 = (const float4*)x;
    const int n4 = 32 * 3 * 224 * 224 / 4;
    for (int i = bx * 256 + threadIdx.x; i < n4; i += 2048 * 256) {
      float4 v = x4[i];
      m = fmaxf(m, fmaxf(fmaxf(fabsf(v.x), fabsf(v.y)), fmaxf(fabsf(v.z), fabsf(v.w))));
    }
  } else {
    const int by = bx - 2048;
    const int grp = by >> 4, xb = by & 15;
    const float* p; int n;
    switch (grp) {
      case 0:  p = w2;  n = 18432; break;
      case 1:  p = wf1; n = 8192;  break;
      case 2:  p = w1;  n = 864;   break;
      default: p = wf2; n = 1280;  break;
    }
    for (int i = xb * 256 + threadIdx.x; i < n; i += 16 * 256)
      m = fmaxf(m, fabsf(p[i]));
  }
  #pragma unroll
  for (int o = 16; o; o >>= 1) m = fmaxf(m, __shfl_xor_sync(0xffffffffu, m, o));
  __shared__ float sm[8];
  if ((threadIdx.x & 31) == 0) sm[threadIdx.x >> 5] = m;
  __syncthreads();
  if (threadIdx.x == 0) {
    float r = sm[0];
    #pragma unroll
    for (int i = 1; i < 8; i++) r = fmaxf(r, sm[i]);
    if (bx < 2048) atomicMax(&g_xabsarr[bx & 255], __float_as_int(r));
    else g_wmaxarr[bx - 2048] = __float_as_int(r);
  }
}

// ========== K2: scales + w1 pack + b1 ======================================
__global__ void k_scales0(const float* __restrict__ w1, const float* __restrict__ b1) {
  __shared__ float sred[8];
  __shared__ float sc[8];
  const int t = threadIdx.x;

  float v = __int_as_float(g_xabsarr[t]);
  #pragma unroll
  for (int o = 16; o; o >>= 1) v = fmaxf(v, __shfl_xor_sync(0xffffffffu, v, o));
  if ((t & 31) == 0) sred[t >> 5] = v;
  __syncthreads();
  if (t == 0) {
    float mx = sred[0];
    #pragma unroll
    for (int i = 1; i < 8; i++) mx = fmaxf(mx, sred[i]);
    float mw2 = 0.f, mf1 = 0.f, mw1 = 0.f, mf2 = 0.f;
    #pragma unroll
    for (int i = 0; i < 16; i++) {
      mw2 = fmaxf(mw2, __int_as_float(g_wmaxarr[i]));
      mf1 = fmaxf(mf1, __int_as_float(g_wmaxarr[16 + i]));
      mw1 = fmaxf(mw1, __int_as_float(g_wmaxarr[32 + i]));
      mf2 = fmaxf(mf2, __int_as_float(g_wmaxarr[48 + i]));
    }
    float s_in = fmaxf(mx, 1e-8f) / 7.0f;
    float sw1  = fmaxf(mw1, 1e-8f) / 7.0f;
    float sw2  = fmaxf(mw2, 1e-8f) / 7.0f;
    float swf1 = fmaxf(mf1, 1e-8f) / 7.0f;
    float swf2 = fmaxf(mf2, 1e-8f) / 7.0f;
    g_s.s_in = s_in; g_s.sw1 = sw1; g_s.sw2 = sw2; g_s.swf1 = swf1; g_s.swf2 = swf2;
    g_s.S1 = s_in * sw1;
    sc[0] = s_in; sc[1] = sw1;
  }
  __syncthreads();
  const float s_in = sc[0], sw1 = sc[1];

  for (int i = t; i < 9 * 32; i += 256) {
    int tap = i / 32, oc = i % 32, kh = tap / 3, kw = tap % 3;
    unsigned v2 = 0;
    #pragma unroll
    for (int c = 0; c < 3; c++) {
      int q = clamp_i((int)rintf(w1[((oc * 3 + c) * 3 + kh) * 3 + kw] / sw1), -8, 7);
      v2 |= ((unsigned)(q & 0xff)) << (8 * c);
    }
    g_w1p[i] = v2;
  }
  if (t < 32) g_b1i[t] = (int)rintf(b1[t] / (s_in * sw1));
}

// ====== K3: quantize x (4 px/thread) + pack w2/fc weights (merged) =========
__global__ void __launch_bounds__(256) k_qxpack(const float* __restrict__ x,
                                                const float* __restrict__ w2,
                                                const float* __restrict__ wf1,
                                                const float* __restrict__ wf2) {
  const int bx = blockIdx.x;
  if (bx < 1568) {
    int g = bx * 256 + threadIdx.x;
    int b = g / 12544, hw4 = (g - b * 12544) * 4;
    const float inv = 1.0f / g_s.s_in;
    float4 c0 = *(const float4*)&x[(b * 3 + 0) * 50176 + hw4];
    float4 c1 = *(const float4*)&x[(b * 3 + 1) * 50176 + hw4];
    float4 c2 = *(const float4*)&x[(b * 3 + 2) * 50176 + hw4];
    uint4 o;
    #pragma unroll
    for (int j = 0; j < 4; j++) {
      float v0 = (&c0.x)[j], v1 = (&c1.x)[j], v2 = (&c2.x)[j];
      int q0 = clamp_i((int)rintf(v0 * inv), -8, 7);
      int q1 = clamp_i((int)rintf(v1 * inv), -8, 7);
      int q2 = clamp_i((int)rintf(v2 * inv), -8, 7);
      (&o.x)[j] = ((unsigned)(q0 & 0xff)) | ((unsigned)(q1 & 0xff) << 8) |
                  ((unsigned)(q2 & 0xff) << 16);
    }
    *(uint4*)&g_qx[b * 50176 + hw4] = o;
    return;
  }
  const int pb = bx - 1568;
  const float sw2 = g_s.sw2, swf1 = g_s.swf1, swf2 = g_s.swf2;
  for (int i = pb * 256 + threadIdx.x; i < 14080; i += 16 * 256) {
    if (i < 4608) {
      int lane = i & 31, kn = i >> 5;
      int n = kn & 7, k = kn >> 3;
      int gg = lane >> 2, tt2 = (lane & 3) * 2;
      int oc = n * 8 + gg;
      float qv[4];
      #pragma unroll
      for (int j = 0; j < 4; j++) {
        int K = k * 16 + tt2 + (j >> 1) * 8 + (j & 1);
        int tap = K >> 5, ic = K & 31;
        int kh = tap / 3, kw = tap % 3;
        qv[j] = (float)clamp_i((int)rintf(w2[((oc * 32 + ic) * 3 + kh) * 3 + kw] / sw2), -8, 7);
      }
      __half2 h0 = __floats2half2_rn(qv[0], qv[1]);
      __half2 h1 = __floats2half2_rn(qv[2], qv[3]);
      uint2 val;
      val.x = *(unsigned*)&h0;
      val.y = *(unsigned*)&h1;
      g_w2frag[i] = val;
    } else if (i < 4608 + 8192) {
      int j = i - 4608;
      g_wf1q[j] = (signed char)clamp_i((int)rintf(wf1[j] / swf1), -8, 7);
    } else {
      int j = i - 4608 - 8192;
      g_wf2q[j] = (signed char)clamp_i((int)rintf(wf2[j] / swf2), -8, 7);
    }
  }
}

// ======== K4a: conv1 pass 1 — max only (no stores) =========================
__global__ void __launch_bounds__(256) k_conv1max() {
  __shared__ int   s_in[340];
  __shared__ uint4 s_w[18];
  const int bz = blockIdx.z;
  const int b = bz >> 2, ocg = bz & 3;
  const int h0 = blockIdx.y * 8, w0 = blockIdx.x * 32;
  const int t = threadIdx.x;

  if (t < 18)
    s_w[t] = *(const uint4*)&g_w1p[(t >> 1) * 32 + ocg * 8 + (t & 1) * 4];
  for (int i = t; i < 340; i += 256) {
    int row = i / 34, col = i % 34;
    int h = h0 + row, w = w0 + col;
    int v = 0;
    if (h < 224 && w < 224) v = (int)g_qx[(b * 224 + h) * 224 + w];
    s_in[i] = v;
  }
  __syncthreads();

  const int ty = t >> 5, tx = t & 31;
  int acc[8];
  #pragma unroll
  for (int k = 0; k < 8; k++) acc[k] = g_b1i[ocg * 8 + k];

  #pragma unroll
  for (int kh = 0; kh < 3; kh++) {
    #pragma unroll
    for (int kw = 0; kw < 3; kw++) {
      int a = s_in[(ty + kh) * 34 + tx + kw];
      uint4 wa = s_w[(kh * 3 + kw) * 2];
      uint4 wb = s_w[(kh * 3 + kw) * 2 + 1];
      acc[0] = __dp4a(a, (int)wa.x, acc[0]);
      acc[1] = __dp4a(a, (int)wa.y, acc[1]);
      acc[2] = __dp4a(a, (int)wa.z, acc[2]);
      acc[3] = __dp4a(a, (int)wa.w, acc[3]);
      acc[4] = __dp4a(a, (int)wb.x, acc[4]);
      acc[5] = __dp4a(a, (int)wb.y, acc[5]);
      acc[6] = __dp4a(a, (int)wb.z, acc[6]);
      acc[7] = __dp4a(a, (int)wb.w, acc[7]);
    }
  }

  const int oh = h0 + ty, ow = w0 + tx;
  int mloc = 0;
  if (oh < 222 && ow < 222) {
    #pragma unroll
    for (int k = 0; k < 8; k++) mloc = max(mloc, acc[k]);
  }
  mloc = __reduce_max_sync(0xffffffffu, mloc);
  __shared__ int smx[8];
  if ((t & 31) == 0) smx[t >> 5] = mloc;
  __syncthreads();
  if (t == 0) {
    int m = smx[0];
    #pragma unroll
    for (int i = 1; i < 8; i++) m = max(m, smx[i]);
    atomicMax(&g_max1arr[(blockIdx.x + 7 * (blockIdx.y + 28 * blockIdx.z)) & 255], m);
  }
}

// ================= K5: scales after conv1 ==================================
__global__ void k_scales1(const float* __restrict__ b2) {
  const int t = threadIdx.x;
  int v = g_max1arr[t];
  v = __reduce_max_sync(0xffffffffu, v);
  __shared__ int   smx[8];
  __shared__ float sc[2];
  if ((t & 31) == 0) smx[t >> 5] = v;
  __syncthreads();
  if (t == 0) {
    int mm = smx[0];
    #pragma unroll
    for (int i = 1; i < 8; i++) mm = max(mm, smx[i]);
    float S1 = g_s.S1;
    float my = fmaxf((float)mm * S1, 1e-8f);
    float s1 = my / 15.0f;
    g_s.s1 = s1;
    g_s.f1 = 15.0f * S1 / my;
    float S2 = s1 * g_s.sw2;
    g_s.S2 = S2;
    sc[0] = s1; sc[1] = g_s.sw2;
  }
  __syncthreads();
  if (t < 64) g_b2i[t] = (int)rintf(b2[t] / (sc[0] * sc[1]));
}

// ======== K4b: conv1 pass 2 — recompute + relu4 quant -> q1 u8 =============
__global__ void __launch_bounds__(256) k_conv1q() {
  __shared__ int   s_in[340];
  __shared__ uint4 s_w[18];
  const int bz = blockIdx.z;
  const int b = bz >> 2, ocg = bz & 3;
  const int h0 = blockIdx.y * 8, w0 = blockIdx.x * 32;
  const int t = threadIdx.x;

  if (t < 18)
    s_w[t] = *(const uint4*)&g_w1p[(t >> 1) * 32 + ocg * 8 + (t & 1) * 4];
  for (int i = t; i < 340; i += 256) {
    int row = i / 34, col = i % 34;
    int h = h0 + row, w = w0 + col;
    int v = 0;
    if (h < 224 && w < 224) v = (int)g_qx[(b * 224 + h) * 224 + w];
    s_in[i] = v;
  }
  __syncthreads();

  const int ty = t >> 5, tx = t & 31;
  int acc[8];
  #pragma unroll
  for (int k = 0; k < 8; k++) acc[k] = g_b1i[ocg * 8 + k];

  #pragma unroll
  for (int kh = 0; kh < 3; kh++) {
    #pragma unroll
    for (int kw = 0; kw < 3; kw++) {
      int a = s_in[(ty + kh) * 34 + tx + kw];
      uint4 wa = s_w[(kh * 3 + kw) * 2];
      uint4 wb = s_w[(kh * 3 + kw) * 2 + 1];
      acc[0] = __dp4a(a, (int)wa.x, acc[0]);
      acc[1] = __dp4a(a, (int)wa.y, acc[1]);
      acc[2] = __dp4a(a, (int)wa.z, acc[2]);
      acc[3] = __dp4a(a, (int)wa.w, acc[3]);
      acc[4] = __dp4a(a, (int)wb.x, acc[4]);
      acc[5] = __dp4a(a, (int)wb.y, acc[5]);
      acc[6] = __dp4a(a, (int)wb.z, acc[6]);
      acc[7] = __dp4a(a, (int)wb.w, acc[7]);
    }
  }

  const int oh = h0 + ty, ow = w0 + tx;
  if (oh < 222 && ow < 222) {
    const float f1 = g_s.f1;
    unsigned q[8];
    #pragma unroll
    for (int k = 0; k < 8; k++)
      q[k] = (unsigned)clamp_i((int)rintf((float)acc[k] * f1), 0, 15);
    uint2 o;
    o.x = q[0] | (q[1] << 8) | (q[2] << 16) | (q[3] << 24);
    o.y = q[4] | (q[5] << 8) | (q[6] << 16) | (q[7] << 24);
    *(uint2*)&g_q1[(size_t)((b * 222 + oh) * 222 + ow) * 32 + ocg * 8] = o;
  }
}

// ====== shared conv2 tile machinery (patch + mainloop) =====================
static constexpr int TILES_TOTAL = 32 * 55 * 7;   // 12320
static constexpr int TPB = 5;
static constexpr int CONV2_GRID = TILES_TOTAL / TPB;  // 2464

// load patch (u8 -> fp16, stride 20 words) for tile (b, h0, w0)
DINL void conv2_load_patch(unsigned* s_patch, int t, int b, int h0, int w0) {
  for (int i = t; i < 408; i += 256) {
    int pix = i >> 1, sub = i & 1;
    int r = pix / 34, c = pix % 34;
    int w = w0 + c;
    uint4 o0 = make_uint4(0, 0, 0, 0), o1 = make_uint4(0, 0, 0, 0);
    if (w < 222) {
      uint4 v = ((const uint4*)(g_q1 + ((size_t)(b * 222 + h0 + r) * 222 + w) * 32))[sub];
      o0.x = u8lo_to_h2(v.x); o0.y = u8hi_to_h2(v.x);
      o0.z = u8lo_to_h2(v.y); o0.w = u8hi_to_h2(v.y);
      o1.x = u8lo_to_h2(v.z); o1.y = u8hi_to_h2(v.z);
      o1.z = u8lo_to_h2(v.w); o1.w = u8hi_to_h2(v.w);
    }
    ((uint4*)s_patch)[pix * 5 + sub * 2]     = o0;
    ((uint4*)s_patch)[pix * 5 + sub * 2 + 1] = o1;
  }
}

#define CONV2_MAINLOOP(acc, abase0, abase1, nh, lane) do { \
  _Pragma("unroll") \
  for (int k = 0; k < 18; k++) { \
    const int tap = k >> 1; \
    const int kh = tap / 3, kw = tap - kh * 3; \
    const uint32_t offk = (uint32_t)(((kh * 34 + kw) * 20 + (k & 1) * 8) * 4); \
    unsigned a0[4], a1[4]; \
    asm volatile("ldmatrix.sync.aligned.m8n8.x4.shared.b16 {%0,%1,%2,%3}, [%4];" \
        : "=r"(a0[0]), "=r"(a0[1]), "=r"(a0[2]), "=r"(a0[3]) : "r"((abase0) + offk)); \
    asm volatile("ldmatrix.sync.aligned.m8n8.x4.shared.b16 {%0,%1,%2,%3}, [%4];" \
        : "=r"(a1[0]), "=r"(a1[1]), "=r"(a1[2]), "=r"(a1[3]) : "r"((abase1) + offk)); \
    _Pragma("unroll") \
    for (int n = 0; n < 4; n++) { \
      uint2 bb = g_w2frag[(k * 8 + (nh) * 4 + n) * 32 + (lane)]; \
      asm volatile("mma.sync.aligned.m16n8k16.row.col.f32.f16.f16.f32 " \
          "{%0,%1,%2,%3}, {%4,%5,%6,%7}, {%8,%9}, {%0,%1,%2,%3};" \
          : "+f"(acc[0][n][0]), "+f"(acc[0][n][1]), "+f"(acc[0][n][2]), "+f"(acc[0][n][3]) \
          : "r"(a0[0]), "r"(a0[1]), "r"(a0[2]), "r"(a0[3]), "r"(bb.x), "r"(bb.y)); \
      asm volatile("mma.sync.aligned.m16n8k16.row.col.f32.f16.f16.f32 " \
          "{%0,%1,%2,%3}, {%4,%5,%6,%7}, {%8,%9}, {%0,%1,%2,%3};" \
          : "+f"(acc[1][n][0]), "+f"(acc[1][n][1]), "+f"(acc[1][n][2]), "+f"(acc[1][n][3]) \
          : "r"(a1[0]), "r"(a1[1]), "r"(a1[2]), "r"(a1[3]), "r"(bb.x), "r"(bb.y)); \
    } \
  } \
} while (0)

// ========== K7a: conv2 pass 1 — max only (no y2 stores) ====================
__global__ void __launch_bounds__(256) k_conv2max() {
  __shared__ __align__(16) unsigned s_patch[4080];
  __shared__ float s_bias[64];
  __shared__ int s_red[8];

  const int t = threadIdx.x;
  const int wid = t >> 5, lane = t & 31;
  const int g = lane >> 2, t2 = (lane & 3) * 2;
  const int mq = wid & 3, nh = wid >> 2;

  if (t < 64) s_bias[t] = (float)g_b2i[t];

  const int colb = (lane & 7) + ((lane & 8) ? 8 : 0);
  const int khw = (lane & 16) ? 4 : 0;
  const uint32_t pbase = smem_u32(s_patch);
  const uint32_t abase0 = pbase + (uint32_t)(((mq * 34 + colb) * 20 + khw) * 4);
  const uint32_t abase1 = abase0 + 16 * 20 * 4;

  float mloc = 0.f;

  for (int it = 0; it < TPB; it++) {
    const int T = blockIdx.x * TPB + it;
    const int b = T / 385;
    const int rem = T - b * 385;
    const int rt = rem / 7, ct = rem % 7;
    const int h0 = rt * 4, w0 = ct * 32;

    __syncthreads();
    conv2_load_patch(s_patch, t, b, h0, w0);
    __syncthreads();

    float acc[2][4][4];
    #pragma unroll
    for (int s = 0; s < 2; s++)
      #pragma unroll
      for (int n = 0; n < 4; n++)
        acc[s][n][0] = acc[s][n][1] = acc[s][n][2] = acc[s][n][3] = 0.f;

    CONV2_MAINLOOP(acc, abase0, abase1, nh, lane);

    #pragma unroll
    for (int s = 0; s < 2; s++) {
      const bool ok0 = (w0 + s * 16 + g) < 220;
      const bool ok1 = (w0 + s * 16 + g + 8) < 220;
      #pragma unroll
      for (int n = 0; n < 4; n++) {
        int oc = (nh * 4 + n) * 8 + t2;
        if (ok0) mloc = fmaxf(mloc, fmaxf(acc[s][n][0] + s_bias[oc],
                                          acc[s][n][1] + s_bias[oc + 1]));
        if (ok1) mloc = fmaxf(mloc, fmaxf(acc[s][n][2] + s_bias[oc],
                                          acc[s][n][3] + s_bias[oc + 1]));
      }
    }
  }

  #pragma unroll
  for (int o = 16; o; o >>= 1) mloc = fmaxf(mloc, __shfl_xor_sync(0xffffffffu, mloc, o));
  if ((t & 31) == 0) s_red[wid] = __float_as_int(mloc);
  __syncthreads();
  if (t == 0) {
    int m = s_red[0];
    #pragma unroll
    for (int i = 1; i < 8; i++) m = max(m, s_red[i]);
    atomicMax(&g_max2arr[blockIdx.x & 255], m);
  }
}

// ========== K7b: conv2 pass 2 — recompute + quant + pool ===================
__global__ void __launch_bounds__(256) k_conv2pool() {
  __shared__ __align__(16) unsigned s_patch[4080];
  __shared__ float s_bias[64];
  __shared__ float s_r2;
  __shared__ int s_red[8];
  __shared__ int s_psum[8 * 32];

  const int t = threadIdx.x;
  const int wid = t >> 5, lane = t & 31;
  const int g = lane >> 2, tt = lane & 3, t2 = tt * 2;
  const int mq = wid & 3, nh = wid >> 2;

  if (t < 64) s_bias[t] = (float)g_b2i[t];

  // compute r2 locally from g_max2arr (same math as old k_scales2)
  {
    int v = g_max2arr[t];
    v = __reduce_max_sync(0xffffffffu, v);
    if ((t & 31) == 0) s_red[wid] = v;
    __syncthreads();
    if (t == 0) {
      int mm = s_red[0];
      #pragma unroll
      for (int i = 1; i < 8; i++) mm = max(mm, s_red[i]);
      float S2 = g_s.S2;
      float my = fmaxf(__int_as_float(mm) * S2, 1e-8f);
      s_r2 = 15.0f * S2 / my;
    }
    __syncthreads();
  }
  const float r2 = s_r2;

  const int colb = (lane & 7) + ((lane & 8) ? 8 : 0);
  const int khw = (lane & 16) ? 4 : 0;
  const uint32_t pbase = smem_u32(s_patch);
  const uint32_t abase0 = pbase + (uint32_t)(((mq * 34 + colb) * 20 + khw) * 4);
  const uint32_t abase1 = abase0 + 16 * 20 * 4;

  const int bimg = (blockIdx.x * TPB) / 385;   // constant per block (385 = 5*77)
  int qacc[8];
  #pragma unroll
  for (int j = 0; j < 8; j++) qacc[j] = 0;

  for (int it = 0; it < TPB; it++) {
    const int T = blockIdx.x * TPB + it;
    const int rem = T - bimg * 385;
    const int rt = rem / 7, ct = rem % 7;
    const int h0 = rt * 4, w0 = ct * 32;

    __syncthreads();
    conv2_load_patch(s_patch, t, bimg, h0, w0);
    __syncthreads();

    float acc[2][4][4];
    #pragma unroll
    for (int s = 0; s < 2; s++)
      #pragma unroll
      for (int n = 0; n < 4; n++)
        acc[s][n][0] = acc[s][n][1] = acc[s][n][2] = acc[s][n][3] = 0.f;

    CONV2_MAINLOOP(acc, abase0, abase1, nh, lane);

    #pragma unroll
    for (int s = 0; s < 2; s++) {
      const bool ok0 = (w0 + s * 16 + g) < 220;
      const bool ok1 = (w0 + s * 16 + g + 8) < 220;
      #pragma unroll
      for (int n = 0; n < 4; n++) {
        int oc = (nh * 4 + n) * 8 + t2;
        if (ok0) {
          qacc[n * 2]     += clamp_i((int)rintf((acc[s][n][0] + s_bias[oc]) * r2), 0, 15);
          qacc[n * 2 + 1] += clamp_i((int)rintf((acc[s][n][1] + s_bias[oc + 1]) * r2), 0, 15);
        }
        if (ok1) {
          qacc[n * 2]     += clamp_i((int)rintf((acc[s][n][2] + s_bias[oc]) * r2), 0, 15);
          qacc[n * 2 + 1] += clamp_i((int)rintf((acc[s][n][3] + s_bias[oc + 1]) * r2), 0, 15);
        }
      }
    }
  }

  // reduce qacc over lanes with same tt (xor 4, 8, 16 preserve lane&3)
  #pragma unroll
  for (int j = 0; j < 8; j++) {
    qacc[j] += __shfl_xor_sync(0xffffffffu, qacc[j], 4);
    qacc[j] += __shfl_xor_sync(0xffffffffu, qacc[j], 8);
    qacc[j] += __shfl_xor_sync(0xffffffffu, qacc[j], 16);
  }
  __syncthreads();
  if (lane < 4) {
    #pragma unroll
    for (int j = 0; j < 8; j++) s_psum[wid * 32 + tt * 8 + j] = qacc[j];
  }
  __syncthreads();
  if (t < 64) {
    // oc = t: nh = oc>>5, n = (oc>>3)&3, tt = (oc&7)>>1, d = oc&1; j = n*2+d
    int nh2 = t >> 5, n = (t >> 3) & 3, tt2 = (t & 7) >> 1, d = t & 1;
    int j = n * 2 + d;
    int sum = 0;
    #pragma unroll
    for (int w = 0; w < 4; w++)
      sum += s_psum[(nh2 * 4 + w) * 32 + tt2 * 8 + j];
    atomicAdd(&g_pool[bimg * 64 + t], sum);
  }
}

// ================= K9: head (computes s2 locally) ==========================
__global__ void __launch_bounds__(256) k_head(const float* __restrict__ bf1,
                                              const float* __restrict__ bf2,
                                              float* __restrict__ out) {
  __shared__ float mean[32 * 64];
  __shared__ float y3[32 * 128];
  __shared__ float y4[320];
  __shared__ float red[8];
  __shared__ float s2sh, s3sh;
  const int t = threadIdx.x;

  // s2 from g_max2arr
  {
    int v = g_max2arr[t];
    v = __reduce_max_sync(0xffffffffu, v);
    __shared__ int ired[8];
    if ((t & 31) == 0) ired[t >> 5] = v;
    __syncthreads();
    if (t == 0) {
      int mm = ired[0];
      #pragma unroll
      for (int i = 1; i < 8; i++) mm = max(mm, ired[i]);
      float S2 = g_s.S2;
      float my = fmaxf(__int_as_float(mm) * S2, 1e-8f);
      s2sh = my / 15.0f;
    }
    __syncthreads();
  }
  const float s2 = s2sh;
  const float swf1 = g_s.swf1, swf2 = g_s.swf2;
  const float msc = s2 / 48400.0f;
  for (int i = t; i < 2048; i += 256) mean[i] = (float)g_pool[i] * msc;
  __syncthreads();

  float lmax = 0.f;
  for (int idx = t; idx < 4096; idx += 256) {
    int b = idx >> 7, o = idx & 127;
    const signed char* wr = &g_wf1q[o * 64];
    const float* mr = &mean[b * 64];
    float a = 0.f;
    #pragma unroll 8
    for (int c = 0; c < 64; c++) a += mr[c] * (float)wr[c];
    float bq = rintf(bf1[o] / (s2 * swf1)) * (s2 * swf1);
    float y = swf1 * a + bq;
    y3[idx] = y;
    lmax = fmaxf(lmax, y);
  }
  #pragma unroll
  for (int o = 16; o; o >>= 1) lmax = fmaxf(lmax, __shfl_xor_sync(0xffffffffu, lmax, o));
  if ((t & 31) == 0) red[t >> 5] = lmax;
  __syncthreads();
  if (t == 0) {
    float r = red[0];
    #pragma unroll
    for (int i = 1; i < 8; i++) r = fmaxf(r, red[i]);
    s3sh = fmaxf(r, 1e-8f) / 15.0f;
  }
  __syncthreads();
  const float s3 = s3sh;

  for (int idx = t; idx < 320; idx += 256) {
    int b = idx / 10, k = idx % 10;
    const signed char* wr = &g_wf2q[k * 128];
    const float* yr = &y3[b * 128];
    float a = 0.f;
    #pragma unroll 8
    for (int o = 0; o < 128; o++) {
      int q = clamp_i((int)rintf(yr[o] / s3), 0, 15);
      a += (float)q * (float)wr[o];
    }
    float bq = rintf(bf2[k] / (s3 * swf2)) * (s3 * swf2);
    y4[idx] = s3 * swf2 * a + bq;
  }
  __syncthreads();

  if (t < 32) {
    float mval = -1e30f;
    #pragma unroll
    for (int k = 0; k < 10; k++) mval = fmaxf(mval, y4[t * 10 + k]);
    float ssum = 0.f;
    #pragma unroll
    for (int k = 0; k < 10; k++) ssum += expf(y4[t * 10 + k] - mval);
    float l = logf(ssum);
    #pragma unroll
    for (int k = 0; k < 10; k++) out[t * 10 + k] = y4[t * 10 + k] - mval - l;
  }
}

// ============================= launcher ====================================
extern "C" void kernel_launch(void* const* d_in, const int* in_sizes, int n_in,
                              void* d_out, int out_size) {
  const float* x   = (const float*)d_in[0];
  const float* w1  = (const float*)d_in[1];
  const float* b1  = (const float*)d_in[2];
  const float* w2  = (const float*)d_in[3];
  const float* b2  = (const float*)d_in[4];
  const float* wf1 = (const float*)d_in[5];
  const float* bf1 = (const float*)d_in[6];
  const float* wf2 = (const float*)d_in[7];
  const float* bf2 = (const float*)d_in[8];
  float* out = (float*)d_out;

  k_init<<<1, 256>>>();
  k_abswmax<<<2112, 256>>>(x, w1, w2, wf1, wf2);
  k_scales0<<<1, 256>>>(w1, b1);
  k_qxpack<<<1584, 256>>>(x, w2, wf1, wf2);
  k_conv1max<<<dim3(7, 28, 128), 256>>>();
  k_scales1<<<1, 256>>>(b2);
  k_conv1q<<<dim3(7, 28, 128), 256>>>();
  k_conv2max<<<CONV2_GRID, 256>>>();
  k_conv2pool<<<CONV2_GRID, 256>>>();
  k_head<<<1, 256>>>(bf1, bf2, out);
}

// round 15
// speedup vs baseline: 1.2224x; 1.2224x over previous
#include <cuda_runtime.h>
#include <cuda_fp16.h>
#include <math.h>
#include <stdint.h>

#define DINL __device__ __forceinline__

// ============================== scratch ====================================
struct Scalars {
  float s_in, sw1, sw2, swf1, swf2;
  float S1, s1, f1, S2, s2, r2;
};
__device__ Scalars g_s;
__device__ int g_xabsarr[256];
__device__ int g_wmaxarr[64];    // [tensor 4][block 16] float bits
__device__ int g_max1arr[256];
__device__ int g_max2arr[256];   // float bits (nonneg)

__device__ __align__(16) unsigned      g_qx [32 * 224 * 224];       // packed s8 3ch
__device__ __align__(16) unsigned char g_q1 [32u * 222 * 222 * 32]; // relu4 u8 NHWC
__device__ __align__(16) __half        g_y2h[32u * 48400 * 64];     // conv2 out fp16 NHWC
__device__ int g_pool[32 * 64];
__device__ __align__(16) unsigned g_w1p[9 * 32];
__device__ __align__(16) uint2    g_w2frag[18 * 8 * 32];  // fp16 B frags [(k*8+n)*32+lane]
__device__ signed char g_wf1q[128 * 64];
__device__ signed char g_wf2q[10 * 128];
__device__ int g_b1i[32];
__device__ int g_b2i[64];

// ============================== helpers ====================================
DINL int clamp_i(int v, int lo, int hi) { return v < lo ? lo : (v > hi ? hi : v); }

DINL uint32_t smem_u32(const void* p) {
  uint32_t a;
  asm("{ .reg .u64 t; cvta.to.shared.u64 t, %1; cvt.u32.u64 %0, t; }" : "=r"(a) : "l"(p));
  return a;
}

// exact u8(0..15) pair -> half2 via PRMT + HSUB2
DINL unsigned u8lo_to_h2(unsigned wv) {
  unsigned u = __byte_perm(wv, 0x64646464u, 0x4140);
  __half2 k; *(unsigned*)&k = 0x64006400u;
  __half2 r = __hsub2(*(__half2*)&u, k);
  return *(unsigned*)&r;
}
DINL unsigned u8hi_to_h2(unsigned wv) {
  unsigned u = __byte_perm(wv, 0x64646464u, 0x4342);
  __half2 k; *(unsigned*)&k = 0x64006400u;
  __half2 r = __hsub2(*(__half2*)&u, k);
  return *(unsigned*)&r;
}

// ============================== K0: init ===================================
__global__ void k_init() {
  int t = threadIdx.x;
  if (t < 256) { g_xabsarr[t] = 0; g_max1arr[t] = 0; g_max2arr[t] = 0; }
  if (t < 64) g_wmaxarr[t] = 0;
  for (int i = t; i < 2048; i += 256) g_pool[i] = 0;
}

// ============ K1: |x| max (float4) + weight maxes (merged) =================
__global__ void __launch_bounds__(256) k_abswmax(const float* __restrict__ x,
                                                 const float* __restrict__ w1,
                                                 const float* __restrict__ w2,
                                                 const float* __restrict__ wf1,
                                                 const float* __restrict__ wf2) {
  const int bx = blockIdx.x;
  float m = 0.f;
  if (bx < 2048) {
    const float4* __restrict__ x4 = (const float4*)x;
    const int n4 = 32 * 3 * 224 * 224 / 4;
    for (int i = bx * 256 + threadIdx.x; i < n4; i += 2048 * 256) {
      float4 v = x4[i];
      m = fmaxf(m, fmaxf(fmaxf(fabsf(v.x), fabsf(v.y)), fmaxf(fabsf(v.z), fabsf(v.w))));
    }
  } else {
    const int by = bx - 2048;
    const int grp = by >> 4, xb = by & 15;
    const float* p; int n;
    switch (grp) {
      case 0:  p = w2;  n = 18432; break;
      case 1:  p = wf1; n = 8192;  break;
      case 2:  p = w1;  n = 864;   break;
      default: p = wf2; n = 1280;  break;
    }
    for (int i = xb * 256 + threadIdx.x; i < n; i += 16 * 256)
      m = fmaxf(m, fabsf(p[i]));
  }
  #pragma unroll
  for (int o = 16; o; o >>= 1) m = fmaxf(m, __shfl_xor_sync(0xffffffffu, m, o));
  __shared__ float sm[8];
  if ((threadIdx.x & 31) == 0) sm[threadIdx.x >> 5] = m;
  __syncthreads();
  if (threadIdx.x == 0) {
    float r = sm[0];
    #pragma unroll
    for (int i = 1; i < 8; i++) r = fmaxf(r, sm[i]);
    if (bx < 2048) atomicMax(&g_xabsarr[bx & 255], __float_as_int(r));
    else g_wmaxarr[bx - 2048] = __float_as_int(r);
  }
}

// ========== K2: scales + w1 pack + b1 ======================================
__global__ void k_scales0(const float* __restrict__ w1, const float* __restrict__ b1) {
  __shared__ float sred[8];
  __shared__ float sc[8];
  const int t = threadIdx.x;

  float v = __int_as_float(g_xabsarr[t]);
  #pragma unroll
  for (int o = 16; o; o >>= 1) v = fmaxf(v, __shfl_xor_sync(0xffffffffu, v, o));
  if ((t & 31) == 0) sred[t >> 5] = v;
  __syncthreads();
  if (t == 0) {
    float mx = sred[0];
    #pragma unroll
    for (int i = 1; i < 8; i++) mx = fmaxf(mx, sred[i]);
    float mw2 = 0.f, mf1 = 0.f, mw1 = 0.f, mf2 = 0.f;
    #pragma unroll
    for (int i = 0; i < 16; i++) {
      mw2 = fmaxf(mw2, __int_as_float(g_wmaxarr[i]));
      mf1 = fmaxf(mf1, __int_as_float(g_wmaxarr[16 + i]));
      mw1 = fmaxf(mw1, __int_as_float(g_wmaxarr[32 + i]));
      mf2 = fmaxf(mf2, __int_as_float(g_wmaxarr[48 + i]));
    }
    float s_in = fmaxf(mx, 1e-8f) / 7.0f;
    float sw1  = fmaxf(mw1, 1e-8f) / 7.0f;
    float sw2  = fmaxf(mw2, 1e-8f) / 7.0f;
    float swf1 = fmaxf(mf1, 1e-8f) / 7.0f;
    float swf2 = fmaxf(mf2, 1e-8f) / 7.0f;
    g_s.s_in = s_in; g_s.sw1 = sw1; g_s.sw2 = sw2; g_s.swf1 = swf1; g_s.swf2 = swf2;
    g_s.S1 = s_in * sw1;
    sc[0] = s_in; sc[1] = sw1;
  }
  __syncthreads();
  const float s_in = sc[0], sw1 = sc[1];

  for (int i = t; i < 9 * 32; i += 256) {
    int tap = i / 32, oc = i % 32, kh = tap / 3, kw = tap % 3;
    unsigned v2 = 0;
    #pragma unroll
    for (int c = 0; c < 3; c++) {
      int q = clamp_i((int)rintf(w1[((oc * 3 + c) * 3 + kh) * 3 + kw] / sw1), -8, 7);
      v2 |= ((unsigned)(q & 0xff)) << (8 * c);
    }
    g_w1p[i] = v2;
  }
  if (t < 32) g_b1i[t] = (int)rintf(b1[t] / (s_in * sw1));
}

// ====== K3: quantize x (4 px/thread) + pack w2/fc weights (merged) =========
__global__ void __launch_bounds__(256) k_qxpack(const float* __restrict__ x,
                                                const float* __restrict__ w2,
                                                const float* __restrict__ wf1,
                                                const float* __restrict__ wf2) {
  const int bx = blockIdx.x;
  if (bx < 1568) {
    int g = bx * 256 + threadIdx.x;
    int b = g / 12544, hw4 = (g - b * 12544) * 4;
    const float inv = 1.0f / g_s.s_in;
    float4 c0 = *(const float4*)&x[(b * 3 + 0) * 50176 + hw4];
    float4 c1 = *(const float4*)&x[(b * 3 + 1) * 50176 + hw4];
    float4 c2 = *(const float4*)&x[(b * 3 + 2) * 50176 + hw4];
    uint4 o;
    #pragma unroll
    for (int j = 0; j < 4; j++) {
      float v0 = (&c0.x)[j], v1 = (&c1.x)[j], v2 = (&c2.x)[j];
      int q0 = clamp_i((int)rintf(v0 * inv), -8, 7);
      int q1 = clamp_i((int)rintf(v1 * inv), -8, 7);
      int q2 = clamp_i((int)rintf(v2 * inv), -8, 7);
      (&o.x)[j] = ((unsigned)(q0 & 0xff)) | ((unsigned)(q1 & 0xff) << 8) |
                  ((unsigned)(q2 & 0xff) << 16);
    }
    *(uint4*)&g_qx[b * 50176 + hw4] = o;
    return;
  }
  const int pb = bx - 1568;
  const float sw2 = g_s.sw2, swf1 = g_s.swf1, swf2 = g_s.swf2;
  for (int i = pb * 256 + threadIdx.x; i < 14080; i += 16 * 256) {
    if (i < 4608) {
      int lane = i & 31, kn = i >> 5;
      int n = kn & 7, k = kn >> 3;
      int gg = lane >> 2, tt2 = (lane & 3) * 2;
      int oc = n * 8 + gg;
      float qv[4];
      #pragma unroll
      for (int j = 0; j < 4; j++) {
        int K = k * 16 + tt2 + (j >> 1) * 8 + (j & 1);
        int tap = K >> 5, ic = K & 31;
        int kh = tap / 3, kw = tap % 3;
        qv[j] = (float)clamp_i((int)rintf(w2[((oc * 32 + ic) * 3 + kh) * 3 + kw] / sw2), -8, 7);
      }
      __half2 h0 = __floats2half2_rn(qv[0], qv[1]);
      __half2 h1 = __floats2half2_rn(qv[2], qv[3]);
      uint2 val;
      val.x = *(unsigned*)&h0;
      val.y = *(unsigned*)&h1;
      g_w2frag[i] = val;
    } else if (i < 4608 + 8192) {
      int j = i - 4608;
      g_wf1q[j] = (signed char)clamp_i((int)rintf(wf1[j] / swf1), -8, 7);
    } else {
      int j = i - 4608 - 8192;
      g_wf2q[j] = (signed char)clamp_i((int)rintf(wf2[j] / swf2), -8, 7);
    }
  }
}

// ======== K4a: conv1 pass 1 — max only (no stores) =========================
__global__ void __launch_bounds__(256) k_conv1max() {
  __shared__ int   s_in[340];
  __shared__ uint4 s_w[18];
  const int bz = blockIdx.z;
  const int b = bz >> 2, ocg = bz & 3;
  const int h0 = blockIdx.y * 8, w0 = blockIdx.x * 32;
  const int t = threadIdx.x;

  if (t < 18)
    s_w[t] = *(const uint4*)&g_w1p[(t >> 1) * 32 + ocg * 8 + (t & 1) * 4];
  for (int i = t; i < 340; i += 256) {
    int row = i / 34, col = i % 34;
    int h = h0 + row, w = w0 + col;
    int v = 0;
    if (h < 224 && w < 224) v = (int)g_qx[(b * 224 + h) * 224 + w];
    s_in[i] = v;
  }
  __syncthreads();

  const int ty = t >> 5, tx = t & 31;
  int acc[8];
  #pragma unroll
  for (int k = 0; k < 8; k++) acc[k] = g_b1i[ocg * 8 + k];

  #pragma unroll
  for (int kh = 0; kh < 3; kh++) {
    #pragma unroll
    for (int kw = 0; kw < 3; kw++) {
      int a = s_in[(ty + kh) * 34 + tx + kw];
      uint4 wa = s_w[(kh * 3 + kw) * 2];
      uint4 wb = s_w[(kh * 3 + kw) * 2 + 1];
      acc[0] = __dp4a(a, (int)wa.x, acc[0]);
      acc[1] = __dp4a(a, (int)wa.y, acc[1]);
      acc[2] = __dp4a(a, (int)wa.z, acc[2]);
      acc[3] = __dp4a(a, (int)wa.w, acc[3]);
      acc[4] = __dp4a(a, (int)wb.x, acc[4]);
      acc[5] = __dp4a(a, (int)wb.y, acc[5]);
      acc[6] = __dp4a(a, (int)wb.z, acc[6]);
      acc[7] = __dp4a(a, (int)wb.w, acc[7]);
    }
  }

  const int oh = h0 + ty, ow = w0 + tx;
  int mloc = 0;
  if (oh < 222 && ow < 222) {
    #pragma unroll
    for (int k = 0; k < 8; k++) mloc = max(mloc, acc[k]);
  }
  mloc = __reduce_max_sync(0xffffffffu, mloc);
  __shared__ int smx[8];
  if ((t & 31) == 0) smx[t >> 5] = mloc;
  __syncthreads();
  if (t == 0) {
    int m = smx[0];
    #pragma unroll
    for (int i = 1; i < 8; i++) m = max(m, smx[i]);
    atomicMax(&g_max1arr[(blockIdx.x + 7 * (blockIdx.y + 28 * blockIdx.z)) & 255], m);
  }
}

// ================= K5: scales after conv1 ==================================
__global__ void k_scales1(const float* __restrict__ b2) {
  const int t = threadIdx.x;
  int v = g_max1arr[t];
  v = __reduce_max_sync(0xffffffffu, v);
  __shared__ int   smx[8];
  __shared__ float sc[2];
  if ((t & 31) == 0) smx[t >> 5] = v;
  __syncthreads();
  if (t == 0) {
    int mm = smx[0];
    #pragma unroll
    for (int i = 1; i < 8; i++) mm = max(mm, smx[i]);
    float S1 = g_s.S1;
    float my = fmaxf((float)mm * S1, 1e-8f);
    float s1 = my / 15.0f;
    g_s.s1 = s1;
    g_s.f1 = 15.0f * S1 / my;
    float S2 = s1 * g_s.sw2;
    g_s.S2 = S2;
    sc[0] = s1; sc[1] = g_s.sw2;
  }
  __syncthreads();
  if (t < 64) g_b2i[t] = (int)rintf(b2[t] / (sc[0] * sc[1]));
}

// ======== K4b: conv1 pass 2 — recompute + relu4 quant -> q1 u8 =============
__global__ void __launch_bounds__(256) k_conv1q() {
  __shared__ int   s_in[340];
  __shared__ uint4 s_w[18];
  const int bz = blockIdx.z;
  const int b = bz >> 2, ocg = bz & 3;
  const int h0 = blockIdx.y * 8, w0 = blockIdx.x * 32;
  const int t = threadIdx.x;

  if (t < 18)
    s_w[t] = *(const uint4*)&g_w1p[(t >> 1) * 32 + ocg * 8 + (t & 1) * 4];
  for (int i = t; i < 340; i += 256) {
    int row = i / 34, col = i % 34;
    int h = h0 + row, w = w0 + col;
    int v = 0;
    if (h < 224 && w < 224) v = (int)g_qx[(b * 224 + h) * 224 + w];
    s_in[i] = v;
  }
  __syncthreads();

  const int ty = t >> 5, tx = t & 31;
  int acc[8];
  #pragma unroll
  for (int k = 0; k < 8; k++) acc[k] = g_b1i[ocg * 8 + k];

  #pragma unroll
  for (int kh = 0; kh < 3; kh++) {
    #pragma unroll
    for (int kw = 0; kw < 3; kw++) {
      int a = s_in[(ty + kh) * 34 + tx + kw];
      uint4 wa = s_w[(kh * 3 + kw) * 2];
      uint4 wb = s_w[(kh * 3 + kw) * 2 + 1];
      acc[0] = __dp4a(a, (int)wa.x, acc[0]);
      acc[1] = __dp4a(a, (int)wa.y, acc[1]);
      acc[2] = __dp4a(a, (int)wa.z, acc[2]);
      acc[3] = __dp4a(a, (int)wa.w, acc[3]);
      acc[4] = __dp4a(a, (int)wb.x, acc[4]);
      acc[5] = __dp4a(a, (int)wb.y, acc[5]);
      acc[6] = __dp4a(a, (int)wb.z, acc[6]);
      acc[7] = __dp4a(a, (int)wb.w, acc[7]);
    }
  }

  const int oh = h0 + ty, ow = w0 + tx;
  if (oh < 222 && ow < 222) {
    const float f1 = g_s.f1;
    unsigned q[8];
    #pragma unroll
    for (int k = 0; k < 8; k++)
      q[k] = (unsigned)clamp_i((int)rintf((float)acc[k] * f1), 0, 15);
    uint2 o;
    o.x = q[0] | (q[1] << 8) | (q[2] << 16) | (q[3] << 24);
    o.y = q[4] | (q[5] << 8) | (q[6] << 16) | (q[7] << 24);
    *(uint2*)&g_q1[(size_t)((b * 222 + oh) * 222 + ow) * 32 + ocg * 8] = o;
  }
}

// ========== K7: conv2 single-pass, prefetched patch, NHWC y2 ===============
static constexpr int TILES_TOTAL = 32 * 55 * 7;   // 12320
static constexpr int TPB = 5;
static constexpr int CONV2_GRID = TILES_TOTAL / TPB;  // 2464

__global__ void __launch_bounds__(256) k_conv2mma() {
  __shared__ __align__(16) unsigned s_patch[4608];  // patch 4080 w / stage 128*72 h
  __shared__ float s_bias[64];
  __shared__ int s_red[8];

  const int t = threadIdx.x;
  const int wid = t >> 5, lane = t & 31;
  const int g = lane >> 2, tt = lane & 3, t2 = tt * 2;
  const int mq = wid & 3, nh = wid >> 2;
  __half* s_stage = (__half*)s_patch;

  if (t < 64) s_bias[t] = (float)g_b2i[t];

  const int colb = (lane & 7) + ((lane & 8) ? 8 : 0);
  const int khw = (lane & 16) ? 4 : 0;
  const uint32_t pbase = smem_u32(s_patch);
  const uint32_t abase0 = pbase + (uint32_t)(((mq * 34 + colb) * 20 + khw) * 4);
  const uint32_t abase1 = abase0 + 16 * 20 * 4;

  float mloc = 0.f;

  // raw prefetch registers: items t and t+256 (408 total)
  uint4 raw[2];
  const int i0 = t, i1 = t + 256;

  // fetch tile 0
  {
    const int T = blockIdx.x * TPB;
    const int b = T / 385;
    const int rem = T - b * 385;
    const int rt = rem / 7, ct = rem % 7;
    const int h0 = rt * 4, w0 = ct * 32;
    #pragma unroll
    for (int u = 0; u < 2; u++) {
      int i = u ? i1 : i0;
      raw[u] = make_uint4(0, 0, 0, 0);
      if (i < 408) {
        int pix = i >> 1, sub = i & 1;
        int r = pix / 34, c = pix % 34;
        int w = w0 + c;
        if (w < 222)
          raw[u] = ((const uint4*)(g_q1 + ((size_t)(b * 222 + h0 + r) * 222 + w) * 32))[sub];
      }
    }
  }

  for (int it = 0; it < TPB; it++) {
    const int T = blockIdx.x * TPB + it;
    const int b = T / 385;
    const int rem = T - b * 385;
    const int rt = rem / 7, ct = rem % 7;
    const int h0 = rt * 4, w0 = ct * 32;

    __syncthreads();   // stage reads from previous iteration complete

    // convert + store patch from prefetched registers
    #pragma unroll
    for (int u = 0; u < 2; u++) {
      int i = u ? i1 : i0;
      if (i < 408) {
        int pix = i >> 1, sub = i & 1;
        uint4 v = raw[u];
        uint4 o0, o1;
        o0.x = u8lo_to_h2(v.x); o0.y = u8hi_to_h2(v.x);
        o0.z = u8lo_to_h2(v.y); o0.w = u8hi_to_h2(v.y);
        o1.x = u8lo_to_h2(v.z); o1.y = u8hi_to_h2(v.z);
        o1.z = u8lo_to_h2(v.w); o1.w = u8hi_to_h2(v.w);
        ((uint4*)s_patch)[pix * 5 + sub * 2]     = o0;
        ((uint4*)s_patch)[pix * 5 + sub * 2 + 1] = o1;
      }
    }

    // prefetch next tile's raw data (LDGs in flight during mainloop)
    if (it + 1 < TPB) {
      const int Tn = T + 1;
      const int bn = Tn / 385;
      const int remn = Tn - bn * 385;
      const int rtn = remn / 7, ctn = remn % 7;
      const int h0n = rtn * 4, w0n = ctn * 32;
      #pragma unroll
      for (int u = 0; u < 2; u++) {
        int i = u ? i1 : i0;
        raw[u] = make_uint4(0, 0, 0, 0);
        if (i < 408) {
          int pix = i >> 1, sub = i & 1;
          int r = pix / 34, c = pix % 34;
          int w = w0n + c;
          if (w < 222)
            raw[u] = ((const uint4*)(g_q1 + ((size_t)(bn * 222 + h0n + r) * 222 + w) * 32))[sub];
        }
      }
    }
    __syncthreads();

    // ---- mma mainloop: 18 k-chunks, A via ldmatrix -----------------------
    float acc[2][4][4];
    #pragma unroll
    for (int s = 0; s < 2; s++)
      #pragma unroll
      for (int n = 0; n < 4; n++)
        acc[s][n][0] = acc[s][n][1] = acc[s][n][2] = acc[s][n][3] = 0.f;

    #pragma unroll
    for (int k = 0; k < 18; k++) {
      const int tap = k >> 1;
      const int kh = tap / 3, kw = tap - kh * 3;
      const uint32_t offk = (uint32_t)(((kh * 34 + kw) * 20 + (k & 1) * 8) * 4);
      unsigned a0[4], a1[4];
      asm volatile("ldmatrix.sync.aligned.m8n8.x4.shared.b16 {%0,%1,%2,%3}, [%4];"
          : "=r"(a0[0]), "=r"(a0[1]), "=r"(a0[2]), "=r"(a0[3]) : "r"(abase0 + offk));
      asm volatile("ldmatrix.sync.aligned.m8n8.x4.shared.b16 {%0,%1,%2,%3}, [%4];"
          : "=r"(a1[0]), "=r"(a1[1]), "=r"(a1[2]), "=r"(a1[3]) : "r"(abase1 + offk));
      #pragma unroll
      for (int n = 0; n < 4; n++) {
        uint2 bb = g_w2frag[(k * 8 + nh * 4 + n) * 32 + lane];
        asm volatile("mma.sync.aligned.m16n8k16.row.col.f32.f16.f16.f32 "
            "{%0,%1,%2,%3}, {%4,%5,%6,%7}, {%8,%9}, {%0,%1,%2,%3};"
            : "+f"(acc[0][n][0]), "+f"(acc[0][n][1]), "+f"(acc[0][n][2]), "+f"(acc[0][n][3])
            : "r"(a0[0]), "r"(a0[1]), "r"(a0[2]), "r"(a0[3]), "r"(bb.x), "r"(bb.y));
        asm volatile("mma.sync.aligned.m16n8k16.row.col.f32.f16.f16.f32 "
            "{%0,%1,%2,%3}, {%4,%5,%6,%7}, {%8,%9}, {%0,%1,%2,%3};"
            : "+f"(acc[1][n][0]), "+f"(acc[1][n][1]), "+f"(acc[1][n][2]), "+f"(acc[1][n][3])
            : "r"(a1[0]), "r"(a1[1]), "r"(a1[2]), "r"(a1[3]), "r"(bb.x), "r"(bb.y));
      }
    }
    __syncthreads();   // all warps done reading patch before stage overlay

    // ---- epilogue: bias, exact max (f32), stage fp16 (stride 72) ---------
    #pragma unroll
    for (int s = 0; s < 2; s++) {
      const int p0 = mq * 32 + s * 16 + g, p1 = p0 + 8;
      const bool ok0 = (w0 + s * 16 + g) < 220;
      const bool ok1 = (w0 + s * 16 + g + 8) < 220;
      #pragma unroll
      for (int n = 0; n < 4; n++) {
        int oc = (nh * 4 + n) * 8 + t2;
        float v0 = acc[s][n][0] + s_bias[oc];
        float v1 = acc[s][n][1] + s_bias[oc + 1];
        float v2 = acc[s][n][2] + s_bias[oc];
        float v3 = acc[s][n][3] + s_bias[oc + 1];
        if (ok0) mloc = fmaxf(mloc, fmaxf(v0, v1));
        if (ok1) mloc = fmaxf(mloc, fmaxf(v2, v3));
        *(__half2*)&s_stage[p0 * 72 + oc] = __floats2half2_rn(v0, v1);
        *(__half2*)&s_stage[p1 * 72 + oc] = __floats2half2_rn(v2, v3);
      }
    }
    __syncthreads();

    // ---- coalesced NHWC write-out: 128 px x 8 uint4 (128 B/px) -----------
    for (int i = t; i < 1024; i += 256) {
      int pix = i >> 3, part = i & 7;
      int ow = w0 + (pix & 31);
      if (ow < 220) {
        int oh = h0 + (pix >> 5);
        uint4 v = ((const uint4*)s_stage)[pix * 9 + part];
        ((uint4*)g_y2h)[((size_t)b * 48400 + oh * 220 + ow) * 8 + part] = v;
      }
    }
  }

  // ---- block max -> hashed float-bits atomic -----------------------------
  #pragma unroll
  for (int o = 16; o; o >>= 1) mloc = fmaxf(mloc, __shfl_xor_sync(0xffffffffu, mloc, o));
  if ((t & 31) == 0) s_red[wid] = __float_as_int(mloc);
  __syncthreads();
  if (t == 0) {
    int m = s_red[0];
    #pragma unroll
    for (int i = 1; i < 8; i++) m = max(m, s_red[i]);
    atomicMax(&g_max2arr[blockIdx.x & 255], m);
  }
}

// ================= K7.5: scales after conv2 ================================
__global__ void k_scales2() {
  const int t = threadIdx.x;
  int v = g_max2arr[t];
  v = __reduce_max_sync(0xffffffffu, v);
  __shared__ int smx[8];
  if ((t & 31) == 0) smx[t >> 5] = v;
  __syncthreads();
  if (t == 0) {
    int mm = smx[0];
    #pragma unroll
    for (int i = 1; i < 8; i++) mm = max(mm, smx[i]);
    float maxf = __int_as_float(mm);      // nonneg: int-max == float-max
    float S2 = g_s.S2;
    float my = fmaxf(maxf * S2, 1e-8f);
    g_s.s2 = my / 15.0f;
    g_s.r2 = 15.0f * S2 / my;
  }
}

// ======= K8: quantize y2 (fp16 NHWC) + avg-pool (atomic accumulate) ========
__global__ void __launch_bounds__(256) k_pool() {
  const int b = blockIdx.x / 22;
  const int chunk = blockIdx.x % 22;
  const int px0 = chunk * 2200;
  const float r2 = g_s.r2;
  const int t = threadIdx.x;
  const int part = t & 7;

  int s[8];
  #pragma unroll
  for (int j = 0; j < 8; j++) s[j] = 0;

  const uint4* __restrict__ base = (const uint4*)g_y2h + ((size_t)b * 48400 + px0) * 8;
  for (int i = t; i < 2200 * 8; i += 256) {
    uint4 v = base[i];
    const __half2* h = (const __half2*)&v;
    #pragma unroll
    for (int j = 0; j < 4; j++) {
      float2 f = __half22float2(h[j]);
      s[j * 2]     += clamp_i((int)rintf(f.x * r2), 0, 15);
      s[j * 2 + 1] += clamp_i((int)rintf(f.y * r2), 0, 15);
    }
  }

  #pragma unroll
  for (int j = 0; j < 8; j++) {
    s[j] += __shfl_xor_sync(0xffffffffu, s[j], 8);
    s[j] += __shfl_xor_sync(0xffffffffu, s[j], 16);
  }
  __shared__ int sm[8 * 64];
  if ((t & 31) < 8) {
    #pragma unroll
    for (int j = 0; j < 8; j++) sm[(t >> 5) * 64 + part * 8 + j] = s[j];
  }
  __syncthreads();
  if (t < 64) {
    int tot = 0;
    #pragma unroll
    for (int w = 0; w < 8; w++) tot += sm[w * 64 + t];
    atomicAdd(&g_pool[b * 64 + t], tot);
  }
}

// ================= K9: head ================================================
__global__ void __launch_bounds__(256) k_head(const float* __restrict__ bf1,
                                              const float* __restrict__ bf2,
                                              float* __restrict__ out) {
  __shared__ float mean[32 * 64];
  __shared__ float y3[32 * 128];
  __shared__ float y4[320];
  __shared__ float red[8];
  __shared__ float s3sh;
  const int t = threadIdx.x;

  const float s2 = g_s.s2;
  const float swf1 = g_s.swf1, swf2 = g_s.swf2;
  const float msc = s2 / 48400.0f;
  for (int i = t; i < 2048; i += 256) mean[i] = (float)g_pool[i] * msc;
  __syncthreads();

  float lmax = 0.f;
  for (int idx = t; idx < 4096; idx += 256) {
    int b = idx >> 7, o = idx & 127;
    const signed char* wr = &g_wf1q[o * 64];
    const float* mr = &mean[b * 64];
    float a = 0.f;
    #pragma unroll 8
    for (int c = 0; c < 64; c++) a += mr[c] * (float)wr[c];
    float bq = rintf(bf1[o] / (s2 * swf1)) * (s2 * swf1);
    float y = swf1 * a + bq;
    y3[idx] = y;
    lmax = fmaxf(lmax, y);
  }
  #pragma unroll
  for (int o = 16; o; o >>= 1) lmax = fmaxf(lmax, __shfl_xor_sync(0xffffffffu, lmax, o));
  if ((t & 31) == 0) red[t >> 5] = lmax;
  __syncthreads();
  if (t == 0) {
    float r = red[0];
    #pragma unroll
    for (int i = 1; i < 8; i++) r = fmaxf(r, red[i]);
    s3sh = fmaxf(r, 1e-8f) / 15.0f;
  }
  __syncthreads();
  const float s3 = s3sh;

  for (int idx = t; idx < 320; idx += 256) {
    int b = idx / 10, k = idx % 10;
    const signed char* wr = &g_wf2q[k * 128];
    const float* yr = &y3[b * 128];
    float a = 0.f;
    #pragma unroll 8
    for (int o = 0; o < 128; o++) {
      int q = clamp_i((int)rintf(yr[o] / s3), 0, 15);
      a += (float)q * (float)wr[o];
    }
    float bq = rintf(bf2[k] / (s3 * swf2)) * (s3 * swf2);
    y4[idx] = s3 * swf2 * a + bq;
  }
  __syncthreads();

  if (t < 32) {
    float mval = -1e30f;
    #pragma unroll
    for (int k = 0; k < 10; k++) mval = fmaxf(mval, y4[t * 10 + k]);
    float ssum = 0.f;
    #pragma unroll
    for (int k = 0; k < 10; k++) ssum += expf(y4[t * 10 + k] - mval);
    float l = logf(ssum);
    #pragma unroll
    for (int k = 0; k < 10; k++) out[t * 10 + k] = y4[t * 10 + k] - mval - l;
  }
}

// ============================= launcher ====================================
extern "C" void kernel_launch(void* const* d_in, const int* in_sizes, int n_in,
                              void* d_out, int out_size) {
  const float* x   = (const float*)d_in[0];
  const float* w1  = (const float*)d_in[1];
  const float* b1  = (const float*)d_in[2];
  const float* w2  = (const float*)d_in[3];
  const float* b2  = (const float*)d_in[4];
  const float* wf1 = (const float*)d_in[5];
  const float* bf1 = (const float*)d_in[6];
  const float* wf2 = (const float*)d_in[7];
  const float* bf2 = (const float*)d_in[8];
  float* out = (float*)d_out;

  k_init<<<1, 256>>>();
  k_abswmax<<<2112, 256>>>(x, w1, w2, wf1, wf2);
  k_scales0<<<1, 256>>>(w1, b1);
  k_qxpack<<<1584, 256>>>(x, w2, wf1, wf2);
  k_conv1max<<<dim3(7, 28, 128), 256>>>();
  k_scales1<<<1, 256>>>(b2);
  k_conv1q<<<dim3(7, 28, 128), 256>>>();
  k_conv2mma<<<CONV2_GRID, 256>>>();
  k_scales2<<<1, 256>>>();
  k_pool<<<32 * 22, 256>>>();
  k_head<<<1, 256>>>(bf1, bf2, out);
}

// round 16
// speedup vs baseline: 1.2717x; 1.0403x over previous
#include <cuda_runtime.h>
#include <cuda_fp16.h>
#include <math.h>
#include <stdint.h>

#define DINL __device__ __forceinline__

// ============================== scratch ====================================
struct Scalars {
  float s_in, sw1, sw2, swf1, swf2;
  float S1, s1, f1, S2, s2, r2;
};
__device__ Scalars g_s;
__device__ int g_xabsarr[256];
__device__ int g_wmaxarr[64];    // [tensor 4][block 16] float bits
__device__ int g_max1arr[256];
__device__ int g_max2arr[256];   // float bits (nonneg)

__device__ __align__(16) unsigned g_qx [32 * 224 * 224];        // packed s8 3ch
__device__ __align__(16) uint4    g_q1 [32u * 222 * 222];       // relu4 4-bit x32ch (16B/px)
__device__ __align__(16) __half   g_y2h[32u * 48400 * 64];      // conv2 out fp16 NHWC
__device__ int g_pool[32 * 64];
__device__ __align__(16) unsigned g_w1p[9 * 32];
__device__ __align__(16) uint2    g_w2frag[18 * 8 * 32];  // fp16 B frags [(k*8+n)*32+lane]
__device__ signed char g_wf1q[128 * 64];
__device__ signed char g_wf2q[10 * 128];
__device__ int g_b1i[32];
__device__ int g_b2i[64];

// ============================== helpers ====================================
DINL int clamp_i(int v, int lo, int hi) { return v < lo ? lo : (v > hi ? hi : v); }

DINL uint32_t smem_u32(const void* p) {
  uint32_t a;
  asm("{ .reg .u64 t; cvta.to.shared.u64 t, %1; cvt.u32.u64 %0, t; }" : "=r"(a) : "l"(p));
  return a;
}

// exact u8(0..15) pair -> half2 via PRMT + HSUB2
DINL unsigned u8lo_to_h2(unsigned wv) {
  unsigned u = __byte_perm(wv, 0x64646464u, 0x4140);
  __half2 k; *(unsigned*)&k = 0x64006400u;
  __half2 r = __hsub2(*(__half2*)&u, k);
  return *(unsigned*)&r;
}
DINL unsigned u8hi_to_h2(unsigned wv) {
  unsigned u = __byte_perm(wv, 0x64646464u, 0x4342);
  __half2 k; *(unsigned*)&k = 0x64006400u;
  __half2 r = __hsub2(*(__half2*)&u, k);
  return *(unsigned*)&r;
}

// unpack 8 nibbles (channels 8w..8w+7) -> 4 fp16x2 words
DINL void nib_to_h2x4(unsigned w, unsigned* out) {
  unsigned e = w & 0x0F0F0F0Fu;
  unsigned o = (w >> 4) & 0x0F0F0F0Fu;
  unsigned il = __byte_perm(e, o, 0x5140);   // ch0,ch1,ch2,ch3
  unsigned ih = __byte_perm(e, o, 0x7362);   // ch4,ch5,ch6,ch7
  out[0] = u8lo_to_h2(il);
  out[1] = u8hi_to_h2(il);
  out[2] = u8lo_to_h2(ih);
  out[3] = u8hi_to_h2(ih);
}

// ============================== K0: init ===================================
__global__ void k_init() {
  int t = threadIdx.x;
  if (t < 256) { g_xabsarr[t] = 0; g_max1arr[t] = 0; g_max2arr[t] = 0; }
  if (t < 64) g_wmaxarr[t] = 0;
  for (int i = t; i < 2048; i += 256) g_pool[i] = 0;
}

// ============ K1: |x| max (float4) + weight maxes (merged) =================
__global__ void __launch_bounds__(256) k_abswmax(const float* __restrict__ x,
                                                 const float* __restrict__ w1,
                                                 const float* __restrict__ w2,
                                                 const float* __restrict__ wf1,
                                                 const float* __restrict__ wf2) {
  const int bx = blockIdx.x;
  float m = 0.f;
  if (bx < 2048) {
    const float4* __restrict__ x4 = (const float4*)x;
    const int n4 = 32 * 3 * 224 * 224 / 4;
    for (int i = bx * 256 + threadIdx.x; i < n4; i += 2048 * 256) {
      float4 v = x4[i];
      m = fmaxf(m, fmaxf(fmaxf(fabsf(v.x), fabsf(v.y)), fmaxf(fabsf(v.z), fabsf(v.w))));
    }
  } else {
    const int by = bx - 2048;
    const int grp = by >> 4, xb = by & 15;
    const float* p; int n;
    switch (grp) {
      case 0:  p = w2;  n = 18432; break;
      case 1:  p = wf1; n = 8192;  break;
      case 2:  p = w1;  n = 864;   break;
      default: p = wf2; n = 1280;  break;
    }
    for (int i = xb * 256 + threadIdx.x; i < n; i += 16 * 256)
      m = fmaxf(m, fabsf(p[i]));
  }
  #pragma unroll
  for (int o = 16; o; o >>= 1) m = fmaxf(m, __shfl_xor_sync(0xffffffffu, m, o));
  __shared__ float sm[8];
  if ((threadIdx.x & 31) == 0) sm[threadIdx.x >> 5] = m;
  __syncthreads();
  if (threadIdx.x == 0) {
    float r = sm[0];
    #pragma unroll
    for (int i = 1; i < 8; i++) r = fmaxf(r, sm[i]);
    if (bx < 2048) atomicMax(&g_xabsarr[bx & 255], __float_as_int(r));
    else g_wmaxarr[bx - 2048] = __float_as_int(r);
  }
}

// ========== K2: scales + w1 pack + b1 ======================================
__global__ void k_scales0(const float* __restrict__ w1, const float* __restrict__ b1) {
  __shared__ float sred[8];
  __shared__ float sc[8];
  const int t = threadIdx.x;

  float v = __int_as_float(g_xabsarr[t]);
  #pragma unroll
  for (int o = 16; o; o >>= 1) v = fmaxf(v, __shfl_xor_sync(0xffffffffu, v, o));
  if ((t & 31) == 0) sred[t >> 5] = v;
  __syncthreads();
  if (t == 0) {
    float mx = sred[0];
    #pragma unroll
    for (int i = 1; i < 8; i++) mx = fmaxf(mx, sred[i]);
    float mw2 = 0.f, mf1 = 0.f, mw1 = 0.f, mf2 = 0.f;
    #pragma unroll
    for (int i = 0; i < 16; i++) {
      mw2 = fmaxf(mw2, __int_as_float(g_wmaxarr[i]));
      mf1 = fmaxf(mf1, __int_as_float(g_wmaxarr[16 + i]));
      mw1 = fmaxf(mw1, __int_as_float(g_wmaxarr[32 + i]));
      mf2 = fmaxf(mf2, __int_as_float(g_wmaxarr[48 + i]));
    }
    float s_in = fmaxf(mx, 1e-8f) / 7.0f;
    float sw1  = fmaxf(mw1, 1e-8f) / 7.0f;
    float sw2  = fmaxf(mw2, 1e-8f) / 7.0f;
    float swf1 = fmaxf(mf1, 1e-8f) / 7.0f;
    float swf2 = fmaxf(mf2, 1e-8f) / 7.0f;
    g_s.s_in = s_in; g_s.sw1 = sw1; g_s.sw2 = sw2; g_s.swf1 = swf1; g_s.swf2 = swf2;
    g_s.S1 = s_in * sw1;
    sc[0] = s_in; sc[1] = sw1;
  }
  __syncthreads();
  const float s_in = sc[0], sw1 = sc[1];

  for (int i = t; i < 9 * 32; i += 256) {
    int tap = i / 32, oc = i % 32, kh = tap / 3, kw = tap % 3;
    unsigned v2 = 0;
    #pragma unroll
    for (int c = 0; c < 3; c++) {
      int q = clamp_i((int)rintf(w1[((oc * 3 + c) * 3 + kh) * 3 + kw] / sw1), -8, 7);
      v2 |= ((unsigned)(q & 0xff)) << (8 * c);
    }
    g_w1p[i] = v2;
  }
  if (t < 32) g_b1i[t] = (int)rintf(b1[t] / (s_in * sw1));
}

// ====== K3: quantize x (4 px/thread) + pack w2/fc weights (merged) =========
__global__ void __launch_bounds__(256) k_qxpack(const float* __restrict__ x,
                                                const float* __restrict__ w2,
                                                const float* __restrict__ wf1,
                                                const float* __restrict__ wf2) {
  const int bx = blockIdx.x;
  if (bx < 1568) {
    int g = bx * 256 + threadIdx.x;
    int b = g / 12544, hw4 = (g - b * 12544) * 4;
    const float inv = 1.0f / g_s.s_in;
    float4 c0 = *(const float4*)&x[(b * 3 + 0) * 50176 + hw4];
    float4 c1 = *(const float4*)&x[(b * 3 + 1) * 50176 + hw4];
    float4 c2 = *(const float4*)&x[(b * 3 + 2) * 50176 + hw4];
    uint4 o;
    #pragma unroll
    for (int j = 0; j < 4; j++) {
      float v0 = (&c0.x)[j], v1 = (&c1.x)[j], v2 = (&c2.x)[j];
      int q0 = clamp_i((int)rintf(v0 * inv), -8, 7);
      int q1 = clamp_i((int)rintf(v1 * inv), -8, 7);
      int q2 = clamp_i((int)rintf(v2 * inv), -8, 7);
      (&o.x)[j] = ((unsigned)(q0 & 0xff)) | ((unsigned)(q1 & 0xff) << 8) |
                  ((unsigned)(q2 & 0xff) << 16);
    }
    *(uint4*)&g_qx[b * 50176 + hw4] = o;
    return;
  }
  const int pb = bx - 1568;
  const float sw2 = g_s.sw2, swf1 = g_s.swf1, swf2 = g_s.swf2;
  for (int i = pb * 256 + threadIdx.x; i < 14080; i += 16 * 256) {
    if (i < 4608) {
      int lane = i & 31, kn = i >> 5;
      int n = kn & 7, k = kn >> 3;
      int gg = lane >> 2, tt2 = (lane & 3) * 2;
      int oc = n * 8 + gg;
      float qv[4];
      #pragma unroll
      for (int j = 0; j < 4; j++) {
        int K = k * 16 + tt2 + (j >> 1) * 8 + (j & 1);
        int tap = K >> 5, ic = K & 31;
        int kh = tap / 3, kw = tap % 3;
        qv[j] = (float)clamp_i((int)rintf(w2[((oc * 32 + ic) * 3 + kh) * 3 + kw] / sw2), -8, 7);
      }
      __half2 h0 = __floats2half2_rn(qv[0], qv[1]);
      __half2 h1 = __floats2half2_rn(qv[2], qv[3]);
      uint2 val;
      val.x = *(unsigned*)&h0;
      val.y = *(unsigned*)&h1;
      g_w2frag[i] = val;
    } else if (i < 4608 + 8192) {
      int j = i - 4608;
      g_wf1q[j] = (signed char)clamp_i((int)rintf(wf1[j] / swf1), -8, 7);
    } else {
      int j = i - 4608 - 8192;
      g_wf2q[j] = (signed char)clamp_i((int)rintf(wf2[j] / swf2), -8, 7);
    }
  }
}

// ======== K4a: conv1 pass 1 — max only (no stores) =========================
__global__ void __launch_bounds__(256) k_conv1max() {
  __shared__ int   s_in[340];
  __shared__ uint4 s_w[18];
  const int bz = blockIdx.z;
  const int b = bz >> 2, ocg = bz & 3;
  const int h0 = blockIdx.y * 8, w0 = blockIdx.x * 32;
  const int t = threadIdx.x;

  if (t < 18)
    s_w[t] = *(const uint4*)&g_w1p[(t >> 1) * 32 + ocg * 8 + (t & 1) * 4];
  for (int i = t; i < 340; i += 256) {
    int row = i / 34, col = i % 34;
    int h = h0 + row, w = w0 + col;
    int v = 0;
    if (h < 224 && w < 224) v = (int)g_qx[(b * 224 + h) * 224 + w];
    s_in[i] = v;
  }
  __syncthreads();

  const int ty = t >> 5, tx = t & 31;
  int acc[8];
  #pragma unroll
  for (int k = 0; k < 8; k++) acc[k] = g_b1i[ocg * 8 + k];

  #pragma unroll
  for (int kh = 0; kh < 3; kh++) {
    #pragma unroll
    for (int kw = 0; kw < 3; kw++) {
      int a = s_in[(ty + kh) * 34 + tx + kw];
      uint4 wa = s_w[(kh * 3 + kw) * 2];
      uint4 wb = s_w[(kh * 3 + kw) * 2 + 1];
      acc[0] = __dp4a(a, (int)wa.x, acc[0]);
      acc[1] = __dp4a(a, (int)wa.y, acc[1]);
      acc[2] = __dp4a(a, (int)wa.z, acc[2]);
      acc[3] = __dp4a(a, (int)wa.w, acc[3]);
      acc[4] = __dp4a(a, (int)wb.x, acc[4]);
      acc[5] = __dp4a(a, (int)wb.y, acc[5]);
      acc[6] = __dp4a(a, (int)wb.z, acc[6]);
      acc[7] = __dp4a(a, (int)wb.w, acc[7]);
    }
  }

  const int oh = h0 + ty, ow = w0 + tx;
  int mloc = 0;
  if (oh < 222 && ow < 222) {
    #pragma unroll
    for (int k = 0; k < 8; k++) mloc = max(mloc, acc[k]);
  }
  mloc = __reduce_max_sync(0xffffffffu, mloc);
  __shared__ int smx[8];
  if ((t & 31) == 0) smx[t >> 5] = mloc;
  __syncthreads();
  if (t == 0) {
    int m = smx[0];
    #pragma unroll
    for (int i = 1; i < 8; i++) m = max(m, smx[i]);
    atomicMax(&g_max1arr[(blockIdx.x + 7 * (blockIdx.y + 28 * blockIdx.z)) & 255], m);
  }
}

// ================= K5: scales after conv1 ==================================
__global__ void k_scales1(const float* __restrict__ b2) {
  const int t = threadIdx.x;
  int v = g_max1arr[t];
  v = __reduce_max_sync(0xffffffffu, v);
  __shared__ int   smx[8];
  __shared__ float sc[2];
  if ((t & 31) == 0) smx[t >> 5] = v;
  __syncthreads();
  if (t == 0) {
    int mm = smx[0];
    #pragma unroll
    for (int i = 1; i < 8; i++) mm = max(mm, smx[i]);
    float S1 = g_s.S1;
    float my = fmaxf((float)mm * S1, 1e-8f);
    float s1 = my / 15.0f;
    g_s.s1 = s1;
    g_s.f1 = 15.0f * S1 / my;
    float S2 = s1 * g_s.sw2;
    g_s.S2 = S2;
    sc[0] = s1; sc[1] = g_s.sw2;
  }
  __syncthreads();
  if (t < 64) g_b2i[t] = (int)rintf(b2[t] / (sc[0] * sc[1]));
}

// ==== K4b: conv1 pass 2 — all 32 oc per thread, nibble q1, coalesced =======
__global__ void __launch_bounds__(256) k_conv1q() {
  __shared__ int s_in[340];
  __shared__ int s_w[288];     // [tap][oc]
  __shared__ int s_b[32];
  const int b = blockIdx.z;
  const int h0 = blockIdx.y * 8, w0 = blockIdx.x * 32;
  const int t = threadIdx.x;

  for (int i = t; i < 288; i += 256) s_w[i] = (int)g_w1p[i];
  if (t < 32) s_b[t] = g_b1i[t];
  for (int i = t; i < 340; i += 256) {
    int row = i / 34, col = i % 34;
    int h = h0 + row, w = w0 + col;
    int v = 0;
    if (h < 224 && w < 224) v = (int)g_qx[(b * 224 + h) * 224 + w];
    s_in[i] = v;
  }
  __syncthreads();

  const int ty = t >> 5, tx = t & 31;
  const int oh = h0 + ty, ow = w0 + tx;
  if (oh >= 222 || ow >= 222) return;

  int acc[32];
  #pragma unroll
  for (int j = 0; j < 32; j++) acc[j] = s_b[j];

  #pragma unroll
  for (int kh = 0; kh < 3; kh++) {
    #pragma unroll
    for (int kw = 0; kw < 3; kw++) {
      int a = s_in[(ty + kh) * 34 + tx + kw];
      const int* wr = &s_w[(kh * 3 + kw) * 32];
      #pragma unroll
      for (int j = 0; j < 32; j++) acc[j] = __dp4a(a, wr[j], acc[j]);
    }
  }

  const float f1 = g_s.f1;
  uint4 o;
  #pragma unroll
  for (int wdi = 0; wdi < 4; wdi++) {
    unsigned pk = 0;
    #pragma unroll
    for (int j = 0; j < 8; j++) {
      unsigned q = (unsigned)clamp_i((int)rintf((float)acc[wdi * 8 + j] * f1), 0, 15);
      pk |= q << (4 * j);
    }
    (&o.x)[wdi] = pk;
  }
  g_q1[(size_t)(b * 222 + oh) * 222 + ow] = o;
}

// ========== K7: conv2 single-pass, prefetched nibble patch, NHWC y2 ========
static constexpr int TILES_TOTAL = 32 * 55 * 7;   // 12320
static constexpr int TPB = 5;
static constexpr int CONV2_GRID = TILES_TOTAL / TPB;  // 2464

__global__ void __launch_bounds__(256) k_conv2mma() {
  __shared__ __align__(16) unsigned s_patch[4608];  // patch 4080 w / stage 128*72 h
  __shared__ float s_bias[64];
  __shared__ int s_red[8];

  const int t = threadIdx.x;
  const int wid = t >> 5, lane = t & 31;
  const int g = lane >> 2, tt = lane & 3, t2 = tt * 2;
  const int mq = wid & 3, nh = wid >> 2;
  __half* s_stage = (__half*)s_patch;

  if (t < 64) s_bias[t] = (float)g_b2i[t];

  const int colb = (lane & 7) + ((lane & 8) ? 8 : 0);
  const int khw = (lane & 16) ? 4 : 0;
  const uint32_t pbase = smem_u32(s_patch);
  const uint32_t abase0 = pbase + (uint32_t)(((mq * 34 + colb) * 20 + khw) * 4);
  const uint32_t abase1 = abase0 + 16 * 20 * 4;

  float mloc = 0.f;

  // one pixel (uint4 raw nibbles) per thread, 204 items
  uint4 raw;
  const bool own = t < 204;
  int myr = t / 34, myc = t - myr * 34;

  // fetch tile 0
  {
    const int T = blockIdx.x * TPB;
    const int b = T / 385;
    const int rem = T - b * 385;
    const int rt = rem / 7, ct = rem % 7;
    const int h0 = rt * 4, w0 = ct * 32;
    raw = make_uint4(0, 0, 0, 0);
    if (own && (w0 + myc) < 222)
      raw = g_q1[(size_t)(b * 222 + h0 + myr) * 222 + w0 + myc];
  }

  for (int it = 0; it < TPB; it++) {
    const int T = blockIdx.x * TPB + it;
    const int b = T / 385;
    const int rem = T - b * 385;
    const int rt = rem / 7, ct = rem % 7;
    const int h0 = rt * 4, w0 = ct * 32;

    __syncthreads();   // stage reads from previous iteration complete

    // unpack nibbles -> fp16 patch
    if (own) {
      unsigned o0[4], o1[4], o2[4], o3[4];
      nib_to_h2x4(raw.x, o0);
      nib_to_h2x4(raw.y, o1);
      nib_to_h2x4(raw.z, o2);
      nib_to_h2x4(raw.w, o3);
      uint4* dst = (uint4*)s_patch + t * 5;
      dst[0] = make_uint4(o0[0], o0[1], o0[2], o0[3]);
      dst[1] = make_uint4(o1[0], o1[1], o1[2], o1[3]);
      dst[2] = make_uint4(o2[0], o2[1], o2[2], o2[3]);
      dst[3] = make_uint4(o3[0], o3[1], o3[2], o3[3]);
    }

    // prefetch next tile's raw data
    if (it + 1 < TPB) {
      const int Tn = T + 1;
      const int bn = Tn / 385;
      const int remn = Tn - bn * 385;
      const int rtn = remn / 7, ctn = remn % 7;
      const int h0n = rtn * 4, w0n = ctn * 32;
      raw = make_uint4(0, 0, 0, 0);
      if (own && (w0n + myc) < 222)
        raw = g_q1[(size_t)(bn * 222 + h0n + myr) * 222 + w0n + myc];
    }
    __syncthreads();

    // ---- mma mainloop: 18 k-chunks, A via ldmatrix -----------------------
    float acc[2][4][4];
    #pragma unroll
    for (int s = 0; s < 2; s++)
      #pragma unroll
      for (int n = 0; n < 4; n++)
        acc[s][n][0] = acc[s][n][1] = acc[s][n][2] = acc[s][n][3] = 0.f;

    #pragma unroll
    for (int k = 0; k < 18; k++) {
      const int tap = k >> 1;
      const int kh = tap / 3, kw = tap - kh * 3;
      const uint32_t offk = (uint32_t)(((kh * 34 + kw) * 20 + (k & 1) * 8) * 4);
      unsigned a0[4], a1[4];
      asm volatile("ldmatrix.sync.aligned.m8n8.x4.shared.b16 {%0,%1,%2,%3}, [%4];"
          : "=r"(a0[0]), "=r"(a0[1]), "=r"(a0[2]), "=r"(a0[3]) : "r"(abase0 + offk));
      asm volatile("ldmatrix.sync.aligned.m8n8.x4.shared.b16 {%0,%1,%2,%3}, [%4];"
          : "=r"(a1[0]), "=r"(a1[1]), "=r"(a1[2]), "=r"(a1[3]) : "r"(abase1 + offk));
      #pragma unroll
      for (int n = 0; n < 4; n++) {
        uint2 bb = g_w2frag[(k * 8 + nh * 4 + n) * 32 + lane];
        asm volatile("mma.sync.aligned.m16n8k16.row.col.f32.f16.f16.f32 "
            "{%0,%1,%2,%3}, {%4,%5,%6,%7}, {%8,%9}, {%0,%1,%2,%3};"
            : "+f"(acc[0][n][0]), "+f"(acc[0][n][1]), "+f"(acc[0][n][2]), "+f"(acc[0][n][3])
            : "r"(a0[0]), "r"(a0[1]), "r"(a0[2]), "r"(a0[3]), "r"(bb.x), "r"(bb.y));
        asm volatile("mma.sync.aligned.m16n8k16.row.col.f32.f16.f16.f32 "
            "{%0,%1,%2,%3}, {%4,%5,%6,%7}, {%8,%9}, {%0,%1,%2,%3};"
            : "+f"(acc[1][n][0]), "+f"(acc[1][n][1]), "+f"(acc[1][n][2]), "+f"(acc[1][n][3])
            : "r"(a1[0]), "r"(a1[1]), "r"(a1[2]), "r"(a1[3]), "r"(bb.x), "r"(bb.y));
      }
    }
    __syncthreads();   // all warps done reading patch before stage overlay

    // ---- epilogue: bias, exact max (f32), stage fp16 (stride 72) ---------
    #pragma unroll
    for (int s = 0; s < 2; s++) {
      const int p0 = mq * 32 + s * 16 + g, p1 = p0 + 8;
      const bool ok0 = (w0 + s * 16 + g) < 220;
      const bool ok1 = (w0 + s * 16 + g + 8) < 220;
      #pragma unroll
      for (int n = 0; n < 4; n++) {
        int oc = (nh * 4 + n) * 8 + t2;
        float v0 = acc[s][n][0] + s_bias[oc];
        float v1 = acc[s][n][1] + s_bias[oc + 1];
        float v2 = acc[s][n][2] + s_bias[oc];
        float v3 = acc[s][n][3] + s_bias[oc + 1];
        if (ok0) mloc = fmaxf(mloc, fmaxf(v0, v1));
        if (ok1) mloc = fmaxf(mloc, fmaxf(v2, v3));
        *(__half2*)&s_stage[p0 * 72 + oc] = __floats2half2_rn(v0, v1);
        *(__half2*)&s_stage[p1 * 72 + oc] = __floats2half2_rn(v2, v3);
      }
    }
    __syncthreads();

    // ---- coalesced NHWC write-out: 128 px x 8 uint4 (128 B/px) -----------
    for (int i = t; i < 1024; i += 256) {
      int pix = i >> 3, part = i & 7;
      int ow = w0 + (pix & 31);
      if (ow < 220) {
        int oh = h0 + (pix >> 5);
        uint4 v = ((const uint4*)s_stage)[pix * 9 + part];
        ((uint4*)g_y2h)[((size_t)b * 48400 + oh * 220 + ow) * 8 + part] = v;
      }
    }
  }

  // ---- block max -> hashed float-bits atomic -----------------------------
  #pragma unroll
  for (int o = 16; o; o >>= 1) mloc = fmaxf(mloc, __shfl_xor_sync(0xffffffffu, mloc, o));
  if ((t & 31) == 0) s_red[wid] = __float_as_int(mloc);
  __syncthreads();
  if (t == 0) {
    int m = s_red[0];
    #pragma unroll
    for (int i = 1; i < 8; i++) m = max(m, s_red[i]);
    atomicMax(&g_max2arr[blockIdx.x & 255], m);
  }
}

// ================= K7.5: scales after conv2 ================================
__global__ void k_scales2() {
  const int t = threadIdx.x;
  int v = g_max2arr[t];
  v = __reduce_max_sync(0xffffffffu, v);
  __shared__ int smx[8];
  if ((t & 31) == 0) smx[t >> 5] = v;
  __syncthreads();
  if (t == 0) {
    int mm = smx[0];
    #pragma unroll
    for (int i = 1; i < 8; i++) mm = max(mm, smx[i]);
    float maxf = __int_as_float(mm);      // nonneg: int-max == float-max
    float S2 = g_s.S2;
    float my = fmaxf(maxf * S2, 1e-8f);
    g_s.s2 = my / 15.0f;
    g_s.r2 = 15.0f * S2 / my;
  }
}

// ======= K8: quantize y2 (fp16 NHWC) + avg-pool (atomic accumulate) ========
__global__ void __launch_bounds__(256) k_pool() {
  const int b = blockIdx.x / 22;
  const int chunk = blockIdx.x % 22;
  const int px0 = chunk * 2200;
  const float r2 = g_s.r2;
  const int t = threadIdx.x;
  const int part = t & 7;

  int s[8];
  #pragma unroll
  for (int j = 0; j < 8; j++) s[j] = 0;

  const uint4* __restrict__ base = (const uint4*)g_y2h + ((size_t)b * 48400 + px0) * 8;
  for (int i = t; i < 2200 * 8; i += 256) {
    uint4 v = base[i];
    const __half2* h = (const __half2*)&v;
    #pragma unroll
    for (int j = 0; j < 4; j++) {
      float2 f = __half22float2(h[j]);
      s[j * 2]     += clamp_i((int)rintf(f.x * r2), 0, 15);
      s[j * 2 + 1] += clamp_i((int)rintf(f.y * r2), 0, 15);
    }
  }

  #pragma unroll
  for (int j = 0; j < 8; j++) {
    s[j] += __shfl_xor_sync(0xffffffffu, s[j], 8);
    s[j] += __shfl_xor_sync(0xffffffffu, s[j], 16);
  }
  __shared__ int sm[8 * 64];
  if ((t & 31) < 8) {
    #pragma unroll
    for (int j = 0; j < 8; j++) sm[(t >> 5) * 64 + part * 8 + j] = s[j];
  }
  __syncthreads();
  if (t < 64) {
    int tot = 0;
    #pragma unroll
    for (int w = 0; w < 8; w++) tot += sm[w * 64 + t];
    atomicAdd(&g_pool[b * 64 + t], tot);
  }
}

// ================= K9: head ================================================
__global__ void __launch_bounds__(256) k_head(const float* __restrict__ bf1,
                                              const float* __restrict__ bf2,
                                              float* __restrict__ out) {
  __shared__ float mean[32 * 64];
  __shared__ float y3[32 * 128];
  __shared__ float y4[320];
  __shared__ float red[8];
  __shared__ float s3sh;
  const int t = threadIdx.x;

  const float s2 = g_s.s2;
  const float swf1 = g_s.swf1, swf2 = g_s.swf2;
  const float msc = s2 / 48400.0f;
  for (int i = t; i < 2048; i += 256) mean[i] = (float)g_pool[i] * msc;
  __syncthreads();

  float lmax = 0.f;
  for (int idx = t; idx < 4096; idx += 256) {
    int b = idx >> 7, o = idx & 127;
    const signed char* wr = &g_wf1q[o * 64];
    const float* mr = &mean[b * 64];
    float a = 0.f;
    #pragma unroll 8
    for (int c = 0; c < 64; c++) a += mr[c] * (float)wr[c];
    float bq = rintf(bf1[o] / (s2 * swf1)) * (s2 * swf1);
    float y = swf1 * a + bq;
    y3[idx] = y;
    lmax = fmaxf(lmax, y);
  }
  #pragma unroll
  for (int o = 16; o; o >>= 1) lmax = fmaxf(lmax, __shfl_xor_sync(0xffffffffu, lmax, o));
  if ((t & 31) == 0) red[t >> 5] = lmax;
  __syncthreads();
  if (t == 0) {
    float r = red[0];
    #pragma unroll
    for (int i = 1; i < 8; i++) r = fmaxf(r, red[i]);
    s3sh = fmaxf(r, 1e-8f) / 15.0f;
  }
  __syncthreads();
  const float s3 = s3sh;

  for (int idx = t; idx < 320; idx += 256) {
    int b = idx / 10, k = idx % 10;
    const signed char* wr = &g_wf2q[k * 128];
    const float* yr = &y3[b * 128];
    float a = 0.f;
    #pragma unroll 8
    for (int o = 0; o < 128; o++) {
      int q = clamp_i((int)rintf(yr[o] / s3), 0, 15);
      a += (float)q * (float)wr[o];
    }
    float bq = rintf(bf2[k] / (s3 * swf2)) * (s3 * swf2);
    y4[idx] = s3 * swf2 * a + bq;
  }
  __syncthreads();

  if (t < 32) {
    float mval = -1e30f;
    #pragma unroll
    for (int k = 0; k < 10; k++) mval = fmaxf(mval, y4[t * 10 + k]);
    float ssum = 0.f;
    #pragma unroll
    for (int k = 0; k < 10; k++) ssum += expf(y4[t * 10 + k] - mval);
    float l = logf(ssum);
    #pragma unroll
    for (int k = 0; k < 10; k++) out[t * 10 + k] = y4[t * 10 + k] - mval - l;
  }
}

// ============================= launcher ====================================
extern "C" void kernel_launch(void* const* d_in, const int* in_sizes, int n_in,
                              void* d_out, int out_size) {
  const float* x   = (const float*)d_in[0];
  const float* w1  = (const float*)d_in[1];
  const float* b1  = (const float*)d_in[2];
  const float* w2  = (const float*)d_in[3];
  const float* b2  = (const float*)d_in[4];
  const float* wf1 = (const float*)d_in[5];
  const float* bf1 = (const float*)d_in[6];
  const float* wf2 = (const float*)d_in[7];
  const float* bf2 = (const float*)d_in[8];
  float* out = (float*)d_out;

  k_init<<<1, 256>>>();
  k_abswmax<<<2112, 256>>>(x, w1, w2, wf1, wf2);
  k_scales0<<<1, 256>>>(w1, b1);
  k_qxpack<<<1584, 256>>>(x, w2, wf1, wf2);
  k_conv1max<<<dim3(7, 28, 128), 256>>>();
  k_scales1<<<1, 256>>>(b2);
  k_conv1q<<<dim3(7, 28, 32), 256>>>();
  k_conv2mma<<<CONV2_GRID, 256>>>();
  k_scales2<<<1, 256>>>();
  k_pool<<<32 * 22, 256>>>();
  k_head<<<1, 256>>>(bf1, bf2, out);
}